// round 9
// baseline (speedup 1.0000x reference)
#include <cuda_runtime.h>
#include <cstdint>
#include <cstddef>

// ---------------- problem constants -----------------------------------------
#define NTOK   65536          // B*S
#define DMODEL 512
#define HID    2048

// GEMM tiling: 128x128 tiles, 2 CTAs/SM
#define BM 128
#define BN 128
#define BK 32                 // fp32 K elements per smem stage (=128B rows)
#define THREADS 256
#define A_BYTES 16384         // 128 rows * 128B
#define STG_BYTES 32768       // A + B
#define SMEM_BYTES (2 * STG_BYTES)    // 64 KB, double buffer

// ---------------- scratch (static device globals; no allocation) ------------
__device__ float g_norm [(size_t)NTOK * DMODEL];
__device__ float g_xattn[(size_t)NTOK * DMODEL];
__device__ float g_h    [(size_t)NTOK * HID];
__device__ float g_y    [(size_t)NTOK * DMODEL];
// pre-rounded (tf32) weights: attn_w | next_w | fc1_w | fc2_w
#define WR_ATTN 0
#define WR_NEXT (512 * 512)
#define WR_FC1  (2 * 512 * 512)
#define WR_FC2  (WR_FC1 + 8 * 2048 * 512)
__device__ float g_wr[(size_t)(2 * 512 * 512 + 2 * 8 * 2048 * 512)];

// ---------------- PTX helpers ------------------------------------------------
__device__ __forceinline__ uint32_t smem_u32(const void* p) {
    uint32_t a;
    asm("{ .reg .u64 t; cvta.to.shared.u64 t, %1; cvt.u32.u64 %0, t; }"
        : "=r"(a) : "l"(p));
    return a;
}
__device__ __forceinline__ float to_tf32(float x) {
    float r;
    asm("cvt.rna.tf32.f32 %0, %1;" : "=f"(r) : "f"(x));
    return r;
}
__device__ __forceinline__ void cp16(uint32_t dst, const void* src) {
    asm volatile("cp.async.cg.shared.global [%0], [%1], 16;"
                 :: "r"(dst), "l"(src) : "memory");
}
__device__ __forceinline__ void cp_commit() {
    asm volatile("cp.async.commit_group;" ::: "memory");
}
template<int N>
__device__ __forceinline__ void cp_wait() {
    asm volatile("cp.async.wait_group %0;" :: "n"(N) : "memory");
}
__device__ __forceinline__ void ldsm4(uint32_t& r0, uint32_t& r1,
                                      uint32_t& r2, uint32_t& r3, uint32_t addr) {
    asm volatile("ldmatrix.sync.aligned.m8n8.x4.shared.b16 {%0,%1,%2,%3}, [%4];"
                 : "=r"(r0), "=r"(r1), "=r"(r2), "=r"(r3) : "r"(addr));
}
__device__ __forceinline__ void mma_tf32(float* d, const uint32_t* a,
                                         uint32_t b0, uint32_t b1) {
    asm volatile(
        "mma.sync.aligned.m16n8k8.row.col.f32.tf32.tf32.f32 "
        "{%0,%1,%2,%3}, {%4,%5,%6,%7}, {%8,%9}, {%0,%1,%2,%3};"
        : "+f"(d[0]), "+f"(d[1]), "+f"(d[2]), "+f"(d[3])
        : "r"(a[0]), "r"(a[1]), "r"(a[2]), "r"(a[3]), "r"(b0), "r"(b1));
}
__device__ __forceinline__ float gelu_erf(float x) {
    return 0.5f * x * (1.0f + erff(x * 0.70710678118654752f));
}
__device__ __forceinline__ uint32_t swz(uint32_t off) {
    return off ^ ((off >> 3) & 0x70);
}

// ---------------- fused weight pre-round (fp32 -> tf32 bits), 1 launch -------
#define N4_SMALL (512 * 512 / 4)           // 65536 float4
#define N4_BIG   (8 * 2048 * 512 / 4)      // 2097152 float4
__global__ void __launch_bounds__(256) round_all(
    const float4* __restrict__ s0, const float4* __restrict__ s1,
    const float4* __restrict__ s2, const float4* __restrict__ s3,
    float4* __restrict__ dst)
{
    size_t i = (size_t)blockIdx.x * 256 + threadIdx.x;
    const float4* src;
    size_t off;
    if (i < N4_SMALL)                     { src = s0; off = i; }
    else if (i < 2 * N4_SMALL)            { src = s1; off = i - N4_SMALL; }
    else if (i < 2 * N4_SMALL + N4_BIG)   { src = s2; off = i - 2 * N4_SMALL; }
    else if (i < 2 * N4_SMALL + 2 * N4_BIG) { src = s3; off = i - 2 * N4_SMALL - N4_BIG; }
    else return;
    float4 v = src[off];
    v.x = to_tf32(v.x); v.y = to_tf32(v.y);
    v.z = to_tf32(v.z); v.w = to_tf32(v.w);
    dst[i] = v;
}

// ---------------- LayerNorm (warp per token, tf32-rounded output) ------------
__global__ void __launch_bounds__(256) ln_kernel(
    const float* __restrict__ x, const float* __restrict__ g,
    const float* __restrict__ b, float* __restrict__ out)
{
    const int warp = threadIdx.x >> 5;
    const int lane = threadIdx.x & 31;
    const int token = blockIdx.x * 8 + warp;
    const float* row = x + (size_t)token * DMODEL;

    float4 v[4];
    float s = 0.f, ss = 0.f;
#pragma unroll
    for (int q = 0; q < 4; q++) {
        v[q] = *(const float4*)(row + (size_t)(q * 32 + lane) * 4);
        s  += v[q].x + v[q].y + v[q].z + v[q].w;
        ss  = fmaf(v[q].x, v[q].x, ss);
        ss  = fmaf(v[q].y, v[q].y, ss);
        ss  = fmaf(v[q].z, v[q].z, ss);
        ss  = fmaf(v[q].w, v[q].w, ss);
    }
#pragma unroll
    for (int off = 16; off > 0; off >>= 1) {
        s  += __shfl_xor_sync(0xffffffffu, s,  off);
        ss += __shfl_xor_sync(0xffffffffu, ss, off);
    }
    const float mu  = s * (1.0f / DMODEL);
    const float var = ss * (1.0f / DMODEL) - mu * mu;
    const float rs  = rsqrtf(var + 1e-5f);

    float* orow = out + (size_t)token * DMODEL;
#pragma unroll
    for (int q = 0; q < 4; q++) {
        const int c = (q * 32 + lane) * 4;
        float4 gg = *(const float4*)(g + c);
        float4 bb = *(const float4*)(b + c);
        float4 o;
        o.x = to_tf32((v[q].x - mu) * rs * gg.x + bb.x);
        o.y = to_tf32((v[q].y - mu) * rs * gg.y + bb.y);
        o.z = to_tf32((v[q].z - mu) * rs * gg.z + bb.z);
        o.w = to_tf32((v[q].w - mu) * rs * gg.w + bb.w);
        *(float4*)(orow + c) = o;
    }
}

// ---------------- tf32 mma.sync GEMM, 128x128, 2 CTAs/SM ---------------------
// C[r,c] = sum_k A[r,k] * W[e][c,k] + bias[e][c] (+resid[r,c]) (gelu)
// A and W must be pre-rounded to tf32 bit patterns.
template<bool GELU, bool RESID, bool ROUND_OUT>
__global__ void __launch_bounds__(THREADS, 2)
tc_gemm(const float* __restrict__ A, const float* __restrict__ W,
        const float* __restrict__ bias, const float* __restrict__ resid,
        float* __restrict__ C, int K, int OUTD,
        size_t w_estride, int b_estride)
{
    extern __shared__ char smem[];
    const uint32_t sb = smem_u32(smem);
    const int tid  = threadIdx.x;
    const int wid  = tid >> 5;
    const int lane = tid & 31;
    const int row0 = blockIdx.y * BM;
    const int col0 = blockIdx.x * BN;

    const int e = (row0 >> 12) & 7;              // expert id (4096-token chunks)
    const float* Wp = W + (w_estride ? (size_t)e * w_estride : 0);
    const float* Bp = bias + (b_estride ? e * b_estride : 0);

    const int wm = wid & 1;                      // M half -> 64 rows
    const int wn = wid >> 1;                     // N quarter -> 32 cols

    // ldmatrix lane-derived offsets
    const int aRow  = (lane & 7) + ((lane >> 3) & 1) * 8;
    const int aBSel = (lane >> 4) * 16;
    const int bRow  = (lane & 7) + ((lane >> 4) & 1) * 8;
    const int bBSel = ((lane >> 3) & 1) * 16;

    // cp.async staging indices: 4 A-chunks + 4 B-chunks per thread
    const int sr = tid >> 3;                     // 0..31 base row group
    const int sq = tid & 7;                      // 16B chunk in 128B row

    uint32_t aDst[4], bDst[4];
#pragma unroll
    for (int i = 0; i < 4; i++) {
        uint32_t o = swz((uint32_t)((sr + i * 32) * 128 + sq * 16));
        aDst[i] = o;
        bDst[i] = A_BYTES + o;
    }

    const float* aGm = A  + (size_t)(row0 + sr) * K + sq * 4;
    const float* bGm = Wp + (size_t)(col0 + sr) * K + sq * 4;

    float acc[4][4][4];
#pragma unroll
    for (int i = 0; i < 4; i++)
#pragma unroll
        for (int j = 0; j < 4; j++)
#pragma unroll
            for (int q = 0; q < 4; q++) acc[i][j][q] = 0.f;

    const int nst = K / BK;

    auto issue = [&](int s) {
        const uint32_t base = sb + (uint32_t)(s & 1) * STG_BYTES;
        const int kOff = s * BK;
#pragma unroll
        for (int i = 0; i < 4; i++)
            cp16(base + aDst[i], aGm + (size_t)i * 32 * K + kOff);
#pragma unroll
        for (int i = 0; i < 4; i++)
            cp16(base + bDst[i], bGm + (size_t)i * 32 * K + kOff);
        cp_commit();
    };

    issue(0);

    for (int s = 0; s < nst; ++s) {
        cp_wait<0>();
        __syncthreads();                          // buffer s&1 ready, s-1 consumed
        if (s + 1 < nst) issue(s + 1);            // fill the freed buffer

        const uint32_t sbA = sb + (uint32_t)(s & 1) * STG_BYTES;
        const uint32_t sbB = sbA + A_BYTES;
#pragma unroll
        for (int kk = 0; kk < 4; ++kk) {
            uint32_t af[4][4], bf[2][4];
#pragma unroll
            for (int i = 0; i < 4; ++i) {
                uint32_t off = (uint32_t)((wm * 64 + i * 16 + aRow) * 128 + kk * 32 + aBSel);
                ldsm4(af[i][0], af[i][1], af[i][2], af[i][3], sbA + swz(off));
            }
#pragma unroll
            for (int j = 0; j < 2; ++j) {
                uint32_t off = (uint32_t)((wn * 32 + j * 16 + bRow) * 128 + kk * 32 + bBSel);
                ldsm4(bf[j][0], bf[j][1], bf[j][2], bf[j][3], sbB + swz(off));
            }
#pragma unroll
            for (int i = 0; i < 4; ++i)
#pragma unroll
                for (int j = 0; j < 2; ++j) {
                    mma_tf32(acc[i][2 * j],     af[i], bf[j][0], bf[j][1]);
                    mma_tf32(acc[i][2 * j + 1], af[i], bf[j][2], bf[j][3]);
                }
        }
    }

    // ---- epilogue: direct float2 stores --------------------------------------
    const int gr  = lane >> 2;
    const int ctg = lane & 3;
#pragma unroll
    for (int j = 0; j < 4; ++j) {
        const int col = col0 + wn * 32 + j * 8 + 2 * ctg;
        float2 bv = *(const float2*)(Bp + col);
#pragma unroll
        for (int i = 0; i < 4; ++i) {
            const int ra = row0 + wm * 64 + i * 16 + gr;
            const int rb = ra + 8;
            float2 o0, o1;
            o0.x = acc[i][j][0] + bv.x;  o0.y = acc[i][j][1] + bv.y;
            o1.x = acc[i][j][2] + bv.x;  o1.y = acc[i][j][3] + bv.y;
            if (RESID) {
                float2 r0 = *(const float2*)(resid + (size_t)ra * OUTD + col);
                float2 r1 = *(const float2*)(resid + (size_t)rb * OUTD + col);
                o0.x += r0.x; o0.y += r0.y;
                o1.x += r1.x; o1.y += r1.y;
            }
            if (GELU) {
                o0.x = gelu_erf(o0.x); o0.y = gelu_erf(o0.y);
                o1.x = gelu_erf(o1.x); o1.y = gelu_erf(o1.y);
            }
            if (ROUND_OUT) {
                o0.x = to_tf32(o0.x); o0.y = to_tf32(o0.y);
                o1.x = to_tf32(o1.x); o1.y = to_tf32(o1.y);
            }
            *(float2*)(C + (size_t)ra * OUTD + col) = o0;
            *(float2*)(C + (size_t)rb * OUTD + col) = o1;
        }
    }
}

// ---------------- launch ------------------------------------------------------
extern "C" void kernel_launch(void* const* d_in, const int* in_sizes, int n_in,
                              void* d_out, int out_size)
{
    const float* x      = (const float*)d_in[0];
    const float* ln_g   = (const float*)d_in[1];
    const float* ln_b   = (const float*)d_in[2];
    const float* attn_w = (const float*)d_in[3];
    const float* attn_b = (const float*)d_in[4];
    /* gate_w d_in[5] unused — gating does not affect the output path */
    const float* fc1_w  = (const float*)d_in[6];
    const float* fc1_b  = (const float*)d_in[7];
    const float* fc2_w  = (const float*)d_in[8];
    const float* fc2_b  = (const float*)d_in[9];
    const float* next_w = (const float*)d_in[10];
    const float* next_b = (const float*)d_in[11];
    float* out = (float*)d_out;

    void *p_norm, *p_xattn, *p_h, *p_y, *p_wr;
    cudaGetSymbolAddress(&p_norm,  g_norm);
    cudaGetSymbolAddress(&p_xattn, g_xattn);
    cudaGetSymbolAddress(&p_h,     g_h);
    cudaGetSymbolAddress(&p_y,     g_y);
    cudaGetSymbolAddress(&p_wr,    g_wr);
    float* norm  = (float*)p_norm;
    float* xattn = (float*)p_xattn;
    float* hbuf  = (float*)p_h;
    float* ybuf  = (float*)p_y;
    float* wr    = (float*)p_wr;

    cudaFuncSetAttribute(tc_gemm<false, true,  true>,
                         cudaFuncAttributeMaxDynamicSharedMemorySize, SMEM_BYTES);
    cudaFuncSetAttribute(tc_gemm<true,  false, true>,
                         cudaFuncAttributeMaxDynamicSharedMemorySize, SMEM_BYTES);
    cudaFuncSetAttribute(tc_gemm<false, false, true>,
                         cudaFuncAttributeMaxDynamicSharedMemorySize, SMEM_BYTES);
    cudaFuncSetAttribute(tc_gemm<true,  false, false>,
                         cudaFuncAttributeMaxDynamicSharedMemorySize, SMEM_BYTES);

    // 0) pre-round all weights to tf32 (single fused launch)
    {
        const size_t total4 = 2 * (size_t)N4_SMALL + 2 * (size_t)N4_BIG;
        round_all<<<(unsigned)((total4 + 255) / 256), 256>>>(
            (const float4*)attn_w, (const float4*)next_w,
            (const float4*)fc1_w,  (const float4*)fc2_w, (float4*)wr);
    }

    // 1) LayerNorm (tf32-rounded output)
    ln_kernel<<<NTOK / 8, 256>>>(x, ln_g, ln_b, norm);

    // 2) attn linear + residual (output rounded: feeds fc1)
    tc_gemm<false, true, true><<<dim3(DMODEL / BN, NTOK / BM), THREADS, SMEM_BYTES>>>(
        norm, wr + WR_ATTN, attn_b, x, xattn, DMODEL, DMODEL, 0, 0);

    // 3) fc1 + gelu (per-expert; output rounded: feeds fc2)
    tc_gemm<true, false, true><<<dim3(HID / BN, NTOK / BM), THREADS, SMEM_BYTES>>>(
        xattn, wr + WR_FC1, fc1_b, nullptr, hbuf, DMODEL, HID,
        (size_t)HID * DMODEL, HID);

    // 4) fc2 (per-expert; output rounded: feeds next)
    tc_gemm<false, false, true><<<dim3(DMODEL / BN, NTOK / BM), THREADS, SMEM_BYTES>>>(
        hbuf, wr + WR_FC2, fc2_b, nullptr, ybuf, HID, DMODEL,
        (size_t)DMODEL * HID, DMODEL);

    // 5) next linear + gelu (final output, no rounding)
    tc_gemm<true, false, false><<<dim3(DMODEL / BN, NTOK / BM), THREADS, SMEM_BYTES>>>(
        ybuf, wr + WR_NEXT, next_b, nullptr, out, DMODEL, DMODEL, 0, 0);
}

// round 10
// speedup vs baseline: 1.1896x; 1.1896x over previous
#include <cuda_runtime.h>
#include <cstdint>
#include <cstddef>

// ---------------- problem constants -----------------------------------------
#define NTOK   65536          // B*S
#define DMODEL 512
#define HID    2048

// GEMM tiling: 128x256 tiles, BK=64 (two 128B column-blocks), double buffer
#define BM 128
#define BN 256
#define BK 64
#define THREADS 256
#define A_BLK 16384           // 128 rows * 128B
#define B_BLK 32768           // 256 rows * 128B
#define A_BYTES (2 * A_BLK)   // 32 KB (2 column blocks)
#define STG_BYTES (2 * A_BLK + 2 * B_BLK)   // 96 KB
#define SMEM_BYTES (2 * STG_BYTES)          // 192 KB

// ---------------- scratch (static device globals; no allocation) ------------
__device__ float g_norm [(size_t)NTOK * DMODEL];
__device__ float g_xattn[(size_t)NTOK * DMODEL];
__device__ float g_h    [(size_t)NTOK * HID];
__device__ float g_y    [(size_t)NTOK * DMODEL];
// pre-rounded (tf32) weights: attn_w | next_w | fc1_w | fc2_w
#define WR_ATTN 0
#define WR_NEXT (512 * 512)
#define WR_FC1  (2 * 512 * 512)
#define WR_FC2  (WR_FC1 + 8 * 2048 * 512)
__device__ float g_wr[(size_t)(2 * 512 * 512 + 2 * 8 * 2048 * 512)];

// ---------------- PTX helpers ------------------------------------------------
__device__ __forceinline__ uint32_t smem_u32(const void* p) {
    uint32_t a;
    asm("{ .reg .u64 t; cvta.to.shared.u64 t, %1; cvt.u32.u64 %0, t; }"
        : "=r"(a) : "l"(p));
    return a;
}
__device__ __forceinline__ float to_tf32(float x) {
    float r;
    asm("cvt.rna.tf32.f32 %0, %1;" : "=f"(r) : "f"(x));
    return r;
}
__device__ __forceinline__ void cp16(uint32_t dst, const void* src) {
    asm volatile("cp.async.cg.shared.global [%0], [%1], 16;"
                 :: "r"(dst), "l"(src) : "memory");
}
__device__ __forceinline__ void cp_commit() {
    asm volatile("cp.async.commit_group;" ::: "memory");
}
template<int N>
__device__ __forceinline__ void cp_wait() {
    asm volatile("cp.async.wait_group %0;" :: "n"(N) : "memory");
}
__device__ __forceinline__ void ldsm4(uint32_t& r0, uint32_t& r1,
                                      uint32_t& r2, uint32_t& r3, uint32_t addr) {
    asm volatile("ldmatrix.sync.aligned.m8n8.x4.shared.b16 {%0,%1,%2,%3}, [%4];"
                 : "=r"(r0), "=r"(r1), "=r"(r2), "=r"(r3) : "r"(addr));
}
__device__ __forceinline__ void mma_tf32(float* d, const uint32_t* a,
                                         uint32_t b0, uint32_t b1) {
    asm volatile(
        "mma.sync.aligned.m16n8k8.row.col.f32.tf32.tf32.f32 "
        "{%0,%1,%2,%3}, {%4,%5,%6,%7}, {%8,%9}, {%0,%1,%2,%3};"
        : "+f"(d[0]), "+f"(d[1]), "+f"(d[2]), "+f"(d[3])
        : "r"(a[0]), "r"(a[1]), "r"(a[2]), "r"(a[3]), "r"(b0), "r"(b1));
}
__device__ __forceinline__ float gelu_erf(float x) {
    return 0.5f * x * (1.0f + erff(x * 0.70710678118654752f));
}
__device__ __forceinline__ uint32_t swz(uint32_t off) {
    return off ^ ((off >> 3) & 0x70);
}

// ---------------- fused weight pre-round (fp32 -> tf32 bits), 1 launch -------
#define N4_SMALL (512 * 512 / 4)           // 65536 float4
#define N4_BIG   (8 * 2048 * 512 / 4)      // 2097152 float4
__global__ void __launch_bounds__(256) round_all(
    const float4* __restrict__ s0, const float4* __restrict__ s1,
    const float4* __restrict__ s2, const float4* __restrict__ s3,
    float4* __restrict__ dst)
{
    size_t i = (size_t)blockIdx.x * 256 + threadIdx.x;
    const float4* src;
    size_t off;
    if (i < N4_SMALL)                       { src = s0; off = i; }
    else if (i < 2 * N4_SMALL)              { src = s1; off = i - N4_SMALL; }
    else if (i < 2 * N4_SMALL + N4_BIG)     { src = s2; off = i - 2 * N4_SMALL; }
    else if (i < 2 * N4_SMALL + 2 * N4_BIG) { src = s3; off = i - 2 * N4_SMALL - N4_BIG; }
    else return;
    float4 v = src[off];
    v.x = to_tf32(v.x); v.y = to_tf32(v.y);
    v.z = to_tf32(v.z); v.w = to_tf32(v.w);
    dst[i] = v;
}

// ---------------- LayerNorm (warp per token, tf32-rounded output) ------------
__global__ void __launch_bounds__(256) ln_kernel(
    const float* __restrict__ x, const float* __restrict__ g,
    const float* __restrict__ b, float* __restrict__ out)
{
    const int warp = threadIdx.x >> 5;
    const int lane = threadIdx.x & 31;
    const int token = blockIdx.x * 8 + warp;
    const float* row = x + (size_t)token * DMODEL;

    float4 v[4];
    float s = 0.f, ss = 0.f;
#pragma unroll
    for (int q = 0; q < 4; q++) {
        v[q] = *(const float4*)(row + (size_t)(q * 32 + lane) * 4);
        s  += v[q].x + v[q].y + v[q].z + v[q].w;
        ss  = fmaf(v[q].x, v[q].x, ss);
        ss  = fmaf(v[q].y, v[q].y, ss);
        ss  = fmaf(v[q].z, v[q].z, ss);
        ss  = fmaf(v[q].w, v[q].w, ss);
    }
#pragma unroll
    for (int off = 16; off > 0; off >>= 1) {
        s  += __shfl_xor_sync(0xffffffffu, s,  off);
        ss += __shfl_xor_sync(0xffffffffu, ss, off);
    }
    const float mu  = s * (1.0f / DMODEL);
    const float var = ss * (1.0f / DMODEL) - mu * mu;
    const float rs  = rsqrtf(var + 1e-5f);

    float* orow = out + (size_t)token * DMODEL;
#pragma unroll
    for (int q = 0; q < 4; q++) {
        const int c = (q * 32 + lane) * 4;
        float4 gg = *(const float4*)(g + c);
        float4 bb = *(const float4*)(b + c);
        float4 o;
        o.x = to_tf32((v[q].x - mu) * rs * gg.x + bb.x);
        o.y = to_tf32((v[q].y - mu) * rs * gg.y + bb.y);
        o.z = to_tf32((v[q].z - mu) * rs * gg.z + bb.z);
        o.w = to_tf32((v[q].w - mu) * rs * gg.w + bb.w);
        *(float4*)(orow + c) = o;
    }
}

// ---------------- tf32 mma.sync GEMM, BK=64, hoisted swizzle addresses -------
// C[r,c] = sum_k A[r,k] * W[e][c,k] + bias[e][c] (+resid[r,c]) (gelu)
// A and W must be pre-rounded to tf32 bit patterns.
template<bool GELU, bool RESID, bool ROUND_OUT>
__global__ void __launch_bounds__(THREADS, 1)
tc_gemm(const float* __restrict__ A, const float* __restrict__ W,
        const float* __restrict__ bias, const float* __restrict__ resid,
        float* __restrict__ C, int K, int OUTD,
        size_t w_estride, int b_estride)
{
    extern __shared__ char smem[];
    const uint32_t sb = smem_u32(smem);
    const int tid  = threadIdx.x;
    const int wid  = tid >> 5;
    const int lane = tid & 31;
    const int row0 = blockIdx.y * BM;
    const int col0 = blockIdx.x * BN;

    const int e = (row0 >> 12) & 7;              // expert id (4096-token chunks)
    const float* Wp = W + (w_estride ? (size_t)e * w_estride : 0);
    const float* Bp = bias + (b_estride ? e * b_estride : 0);

    const int wm = wid & 1;                      // M half -> 64 rows
    const int wn = wid >> 1;                     // N quarter -> 64 cols

    // ldmatrix lane-derived components
    const int aRow  = (lane & 7) + ((lane >> 3) & 1) * 8;
    const int aBSel = (lane >> 4) * 16;
    const int bRow  = (lane & 7) + ((lane >> 4) & 1) * 8;
    const int bBSel = ((lane >> 3) & 1) * 16;

    // hoisted swizzle: swz(R*128 + t) = R*128 + (t ^ ((R&7)<<4)), t<128
    const uint32_t xA = (uint32_t)((aRow & 7) << 4);
    const uint32_t xB = (uint32_t)((bRow & 7) << 4);
    uint32_t rowA[4], rowB[4], ktA[4], ktB[4];
#pragma unroll
    for (int i = 0; i < 4; i++)
        rowA[i] = (uint32_t)((wm * 64 + i * 16 + aRow) * 128);
#pragma unroll
    for (int j = 0; j < 4; j++)
        rowB[j] = (uint32_t)((wn * 64 + j * 16 + bRow) * 128);
#pragma unroll
    for (int t = 0; t < 4; t++) {
        ktA[t] = (uint32_t)(t * 32 + aBSel) ^ xA;
        ktB[t] = (uint32_t)(t * 32 + bBSel) ^ xB;
    }

    // cp.async staging indices
    const int sr = tid >> 3;                     // 0..31 base row group
    const int sq = tid & 7;                      // 16B chunk in 128B row
    const uint32_t stgOff = swz((uint32_t)(sr * 128 + sq * 16));

    const float* aGm = A  + (size_t)(row0 + sr) * K + sq * 4;
    const float* bGm = Wp + (size_t)(col0 + sr) * K + sq * 4;

    float acc[4][8][4];
#pragma unroll
    for (int i = 0; i < 4; i++)
#pragma unroll
        for (int j = 0; j < 8; j++)
#pragma unroll
            for (int q = 0; q < 4; q++) acc[i][j][q] = 0.f;

    const int nst = K / BK;

    // stage layout: A0(16K) A1(16K) B0(32K) B1(32K)
    auto issue = [&](int s) {
        const uint32_t base = sb + (uint32_t)(s & 1) * STG_BYTES;
        const int kOff = s * BK;
#pragma unroll
        for (int blk = 0; blk < 2; blk++) {
#pragma unroll
            for (int i = 0; i < 4; i++)
                cp16(base + blk * A_BLK + stgOff + (uint32_t)(i * 32 * 128),
                     aGm + (size_t)i * 32 * K + kOff + blk * 32);
#pragma unroll
            for (int i = 0; i < 8; i++)
                cp16(base + A_BYTES + blk * B_BLK + stgOff + (uint32_t)(i * 32 * 128),
                     bGm + (size_t)i * 32 * K + kOff + blk * 32);
        }
        cp_commit();
    };

    issue(0);

    for (int s = 0; s < nst; ++s) {
        cp_wait<0>();
        __syncthreads();                          // buffer s&1 ready, s-1 consumed
        if (s + 1 < nst) issue(s + 1);            // fill the freed buffer

        const uint32_t stgA = sb + (uint32_t)(s & 1) * STG_BYTES;
#pragma unroll
        for (int kk = 0; kk < 8; ++kk) {
            const int blk = kk >> 2;
            const int t   = kk & 3;
            const uint32_t sbA = stgA + (uint32_t)(blk * A_BLK) + ktA[t];
            const uint32_t sbB = stgA + A_BYTES + (uint32_t)(blk * B_BLK) + ktB[t];
            uint32_t af[4][4], bf[4][4];
#pragma unroll
            for (int i = 0; i < 4; ++i)
                ldsm4(af[i][0], af[i][1], af[i][2], af[i][3], sbA + rowA[i]);
#pragma unroll
            for (int j = 0; j < 4; ++j)
                ldsm4(bf[j][0], bf[j][1], bf[j][2], bf[j][3], sbB + rowB[j]);
#pragma unroll
            for (int i = 0; i < 4; ++i)
#pragma unroll
                for (int j = 0; j < 4; ++j) {
                    mma_tf32(acc[i][2 * j],     af[i], bf[j][0], bf[j][1]);
                    mma_tf32(acc[i][2 * j + 1], af[i], bf[j][2], bf[j][3]);
                }
        }
    }

    // ---- epilogue: direct float2 stores --------------------------------------
    const int gr  = lane >> 2;
    const int ctg = lane & 3;
#pragma unroll
    for (int j = 0; j < 8; ++j) {
        const int col = col0 + wn * 64 + j * 8 + 2 * ctg;
        float2 bv = *(const float2*)(Bp + col);
#pragma unroll
        for (int i = 0; i < 4; ++i) {
            const int ra = row0 + wm * 64 + i * 16 + gr;
            const int rb = ra + 8;
            float2 o0, o1;
            o0.x = acc[i][j][0] + bv.x;  o0.y = acc[i][j][1] + bv.y;
            o1.x = acc[i][j][2] + bv.x;  o1.y = acc[i][j][3] + bv.y;
            if (RESID) {
                float2 r0 = *(const float2*)(resid + (size_t)ra * OUTD + col);
                float2 r1 = *(const float2*)(resid + (size_t)rb * OUTD + col);
                o0.x += r0.x; o0.y += r0.y;
                o1.x += r1.x; o1.y += r1.y;
            }
            if (GELU) {
                o0.x = gelu_erf(o0.x); o0.y = gelu_erf(o0.y);
                o1.x = gelu_erf(o1.x); o1.y = gelu_erf(o1.y);
            }
            if (ROUND_OUT) {
                o0.x = to_tf32(o0.x); o0.y = to_tf32(o0.y);
                o1.x = to_tf32(o1.x); o1.y = to_tf32(o1.y);
            }
            *(float2*)(C + (size_t)ra * OUTD + col) = o0;
            *(float2*)(C + (size_t)rb * OUTD + col) = o1;
        }
    }
}

// ---------------- launch ------------------------------------------------------
extern "C" void kernel_launch(void* const* d_in, const int* in_sizes, int n_in,
                              void* d_out, int out_size)
{
    const float* x      = (const float*)d_in[0];
    const float* ln_g   = (const float*)d_in[1];
    const float* ln_b   = (const float*)d_in[2];
    const float* attn_w = (const float*)d_in[3];
    const float* attn_b = (const float*)d_in[4];
    /* gate_w d_in[5] unused — gating does not affect the output path */
    const float* fc1_w  = (const float*)d_in[6];
    const float* fc1_b  = (const float*)d_in[7];
    const float* fc2_w  = (const float*)d_in[8];
    const float* fc2_b  = (const float*)d_in[9];
    const float* next_w = (const float*)d_in[10];
    const float* next_b = (const float*)d_in[11];
    float* out = (float*)d_out;

    void *p_norm, *p_xattn, *p_h, *p_y, *p_wr;
    cudaGetSymbolAddress(&p_norm,  g_norm);
    cudaGetSymbolAddress(&p_xattn, g_xattn);
    cudaGetSymbolAddress(&p_h,     g_h);
    cudaGetSymbolAddress(&p_y,     g_y);
    cudaGetSymbolAddress(&p_wr,    g_wr);
    float* norm  = (float*)p_norm;
    float* xattn = (float*)p_xattn;
    float* hbuf  = (float*)p_h;
    float* ybuf  = (float*)p_y;
    float* wr    = (float*)p_wr;

    cudaFuncSetAttribute(tc_gemm<false, true,  true>,
                         cudaFuncAttributeMaxDynamicSharedMemorySize, SMEM_BYTES);
    cudaFuncSetAttribute(tc_gemm<true,  false, true>,
                         cudaFuncAttributeMaxDynamicSharedMemorySize, SMEM_BYTES);
    cudaFuncSetAttribute(tc_gemm<false, false, true>,
                         cudaFuncAttributeMaxDynamicSharedMemorySize, SMEM_BYTES);
    cudaFuncSetAttribute(tc_gemm<true,  false, false>,
                         cudaFuncAttributeMaxDynamicSharedMemorySize, SMEM_BYTES);

    // 0) pre-round all weights to tf32 (single fused launch)
    {
        const size_t total4 = 2 * (size_t)N4_SMALL + 2 * (size_t)N4_BIG;
        round_all<<<(unsigned)((total4 + 255) / 256), 256>>>(
            (const float4*)attn_w, (const float4*)next_w,
            (const float4*)fc1_w,  (const float4*)fc2_w, (float4*)wr);
    }

    // 1) LayerNorm (tf32-rounded output)
    ln_kernel<<<NTOK / 8, 256>>>(x, ln_g, ln_b, norm);

    // 2) attn linear + residual (output rounded: feeds fc1)
    tc_gemm<false, true, true><<<dim3(DMODEL / BN, NTOK / BM), THREADS, SMEM_BYTES>>>(
        norm, wr + WR_ATTN, attn_b, x, xattn, DMODEL, DMODEL, 0, 0);

    // 3) fc1 + gelu (per-expert; output rounded: feeds fc2)
    tc_gemm<true, false, true><<<dim3(HID / BN, NTOK / BM), THREADS, SMEM_BYTES>>>(
        xattn, wr + WR_FC1, fc1_b, nullptr, hbuf, DMODEL, HID,
        (size_t)HID * DMODEL, HID);

    // 4) fc2 (per-expert; output rounded: feeds next)
    tc_gemm<false, false, true><<<dim3(DMODEL / BN, NTOK / BM), THREADS, SMEM_BYTES>>>(
        hbuf, wr + WR_FC2, fc2_b, nullptr, ybuf, HID, DMODEL,
        (size_t)DMODEL * HID, DMODEL);

    // 5) next linear + gelu (final output, no rounding)
    tc_gemm<true, false, false><<<dim3(DMODEL / BN, NTOK / BM), THREADS, SMEM_BYTES>>>(
        ybuf, wr + WR_NEXT, next_b, nullptr, out, DMODEL, DMODEL, 0, 0);
}

// round 11
// speedup vs baseline: 1.1899x; 1.0002x over previous
#include <cuda_runtime.h>
#include <cstdint>
#include <cstddef>

// ---------------- problem constants -----------------------------------------
#define NTOK   65536          // B*S
#define DMODEL 512
#define HID    2048

// GEMM tiling: 128x256 tiles, BK=64 (two 128B column-blocks), double buffer
#define BM 128
#define BN 256
#define BK 64
#define THREADS 256
#define A_BLK 16384           // 128 rows * 128B
#define B_BLK 32768           // 256 rows * 128B
#define A_BYTES (2 * A_BLK)   // 32 KB (2 column blocks)
#define STG_BYTES (2 * A_BLK + 2 * B_BLK)   // 96 KB
#define SMEM_BYTES (2 * STG_BYTES)          // 192 KB

// ---------------- scratch (static device globals; no allocation) ------------
__device__ float g_norm [(size_t)NTOK * DMODEL];
__device__ float g_xattn[(size_t)NTOK * DMODEL];
__device__ float g_h    [(size_t)NTOK * HID];
__device__ float g_y    [(size_t)NTOK * DMODEL];
// pre-rounded (tf32) weights: attn_w | next_w | fc1_w | fc2_w
#define WR_ATTN 0
#define WR_NEXT (512 * 512)
#define WR_FC1  (2 * 512 * 512)
#define WR_FC2  (WR_FC1 + 8 * 2048 * 512)
__device__ float g_wr[(size_t)(2 * 512 * 512 + 2 * 8 * 2048 * 512)];

// ---------------- PTX helpers ------------------------------------------------
__device__ __forceinline__ uint32_t smem_u32(const void* p) {
    uint32_t a;
    asm("{ .reg .u64 t; cvta.to.shared.u64 t, %1; cvt.u32.u64 %0, t; }"
        : "=r"(a) : "l"(p));
    return a;
}
__device__ __forceinline__ float to_tf32(float x) {
    float r;
    asm("cvt.rna.tf32.f32 %0, %1;" : "=f"(r) : "f"(x));
    return r;
}
__device__ __forceinline__ void cp16(uint32_t dst, const void* src) {
    asm volatile("cp.async.cg.shared.global [%0], [%1], 16;"
                 :: "r"(dst), "l"(src) : "memory");
}
__device__ __forceinline__ void cp_commit() {
    asm volatile("cp.async.commit_group;" ::: "memory");
}
template<int N>
__device__ __forceinline__ void cp_wait() {
    asm volatile("cp.async.wait_group %0;" :: "n"(N) : "memory");
}
__device__ __forceinline__ void ldsm4(uint32_t& r0, uint32_t& r1,
                                      uint32_t& r2, uint32_t& r3, uint32_t addr) {
    asm volatile("ldmatrix.sync.aligned.m8n8.x4.shared.b16 {%0,%1,%2,%3}, [%4];"
                 : "=r"(r0), "=r"(r1), "=r"(r2), "=r"(r3) : "r"(addr));
}
__device__ __forceinline__ void mma_tf32(float* d, const uint32_t* a,
                                         uint32_t b0, uint32_t b1) {
    asm volatile(
        "mma.sync.aligned.m16n8k8.row.col.f32.tf32.tf32.f32 "
        "{%0,%1,%2,%3}, {%4,%5,%6,%7}, {%8,%9}, {%0,%1,%2,%3};"
        : "+f"(d[0]), "+f"(d[1]), "+f"(d[2]), "+f"(d[3])
        : "r"(a[0]), "r"(a[1]), "r"(a[2]), "r"(a[3]), "r"(b0), "r"(b1));
}
__device__ __forceinline__ float gelu_erf(float x) {
    return 0.5f * x * (1.0f + erff(x * 0.70710678118654752f));
}
__device__ __forceinline__ uint32_t swz(uint32_t off) {
    return off ^ ((off >> 3) & 0x70);
}

// ---------------- fused weight pre-round (fp32 -> tf32 bits), 1 launch -------
#define N4_SMALL (512 * 512 / 4)           // 65536 float4
#define N4_BIG   (8 * 2048 * 512 / 4)      // 2097152 float4
__global__ void __launch_bounds__(256) round_all(
    const float4* __restrict__ s0, const float4* __restrict__ s1,
    const float4* __restrict__ s2, const float4* __restrict__ s3,
    float4* __restrict__ dst)
{
    size_t i = (size_t)blockIdx.x * 256 + threadIdx.x;
    const float4* src;
    size_t off;
    if (i < N4_SMALL)                       { src = s0; off = i; }
    else if (i < 2 * N4_SMALL)              { src = s1; off = i - N4_SMALL; }
    else if (i < 2 * N4_SMALL + N4_BIG)     { src = s2; off = i - 2 * N4_SMALL; }
    else if (i < 2 * N4_SMALL + 2 * N4_BIG) { src = s3; off = i - 2 * N4_SMALL - N4_BIG; }
    else return;
    float4 v = src[off];
    v.x = to_tf32(v.x); v.y = to_tf32(v.y);
    v.z = to_tf32(v.z); v.w = to_tf32(v.w);
    dst[i] = v;
}

// ---------------- LayerNorm (warp per token, tf32-rounded output) ------------
__global__ void __launch_bounds__(256) ln_kernel(
    const float* __restrict__ x, const float* __restrict__ g,
    const float* __restrict__ b, float* __restrict__ out)
{
    const int warp = threadIdx.x >> 5;
    const int lane = threadIdx.x & 31;
    const int token = blockIdx.x * 8 + warp;
    const float* row = x + (size_t)token * DMODEL;

    float4 v[4];
    float s = 0.f, ss = 0.f;
#pragma unroll
    for (int q = 0; q < 4; q++) {
        v[q] = *(const float4*)(row + (size_t)(q * 32 + lane) * 4);
        s  += v[q].x + v[q].y + v[q].z + v[q].w;
        ss  = fmaf(v[q].x, v[q].x, ss);
        ss  = fmaf(v[q].y, v[q].y, ss);
        ss  = fmaf(v[q].z, v[q].z, ss);
        ss  = fmaf(v[q].w, v[q].w, ss);
    }
#pragma unroll
    for (int off = 16; off > 0; off >>= 1) {
        s  += __shfl_xor_sync(0xffffffffu, s,  off);
        ss += __shfl_xor_sync(0xffffffffu, ss, off);
    }
    const float mu  = s * (1.0f / DMODEL);
    const float var = ss * (1.0f / DMODEL) - mu * mu;
    const float rs  = rsqrtf(var + 1e-5f);

    float* orow = out + (size_t)token * DMODEL;
#pragma unroll
    for (int q = 0; q < 4; q++) {
        const int c = (q * 32 + lane) * 4;
        float4 gg = *(const float4*)(g + c);
        float4 bb = *(const float4*)(b + c);
        float4 o;
        o.x = to_tf32((v[q].x - mu) * rs * gg.x + bb.x);
        o.y = to_tf32((v[q].y - mu) * rs * gg.y + bb.y);
        o.z = to_tf32((v[q].z - mu) * rs * gg.z + bb.z);
        o.w = to_tf32((v[q].w - mu) * rs * gg.w + bb.w);
        *(float4*)(orow + c) = o;
    }
}

// ---------------- tf32 mma.sync GEMM, BK=64, fragment double-buffering -------
// C[r,c] = sum_k A[r,k] * W[e][c,k] + bias[e][c] (+resid[r,c]) (gelu)
// A and W must be pre-rounded to tf32 bit patterns.
template<bool GELU, bool RESID, bool ROUND_OUT>
__global__ void __launch_bounds__(THREADS, 1)
tc_gemm(const float* __restrict__ A, const float* __restrict__ W,
        const float* __restrict__ bias, const float* __restrict__ resid,
        float* __restrict__ C, int K, int OUTD,
        size_t w_estride, int b_estride)
{
    extern __shared__ char smem[];
    const uint32_t sb = smem_u32(smem);
    const int tid  = threadIdx.x;
    const int wid  = tid >> 5;
    const int lane = tid & 31;
    const int row0 = blockIdx.y * BM;
    const int col0 = blockIdx.x * BN;

    const int e = (row0 >> 12) & 7;              // expert id (4096-token chunks)
    const float* Wp = W + (w_estride ? (size_t)e * w_estride : 0);
    const float* Bp = bias + (b_estride ? e * b_estride : 0);

    const int wm = wid & 1;                      // M half -> 64 rows
    const int wn = wid >> 1;                     // N quarter -> 64 cols

    // ldmatrix lane-derived components
    const int aRow  = (lane & 7) + ((lane >> 3) & 1) * 8;
    const int aBSel = (lane >> 4) * 16;
    const int bRow  = (lane & 7) + ((lane >> 4) & 1) * 8;
    const int bBSel = ((lane >> 3) & 1) * 16;

    // hoisted swizzle: swz(R*128 + t) = R*128 + (t ^ ((R&7)<<4)), t<128
    const uint32_t xA = (uint32_t)((aRow & 7) << 4);
    const uint32_t xB = (uint32_t)((bRow & 7) << 4);
    uint32_t rowA[4], rowB[4], ktA[4], ktB[4];
#pragma unroll
    for (int i = 0; i < 4; i++)
        rowA[i] = (uint32_t)((wm * 64 + i * 16 + aRow) * 128);
#pragma unroll
    for (int j = 0; j < 4; j++)
        rowB[j] = (uint32_t)((wn * 64 + j * 16 + bRow) * 128);
#pragma unroll
    for (int t = 0; t < 4; t++) {
        ktA[t] = (uint32_t)(t * 32 + aBSel) ^ xA;
        ktB[t] = (uint32_t)(t * 32 + bBSel) ^ xB;
    }

    // cp.async staging indices
    const int sr = tid >> 3;                     // 0..31 base row group
    const int sq = tid & 7;                      // 16B chunk in 128B row
    const uint32_t stgOff = swz((uint32_t)(sr * 128 + sq * 16));

    const float* aGm = A  + (size_t)(row0 + sr) * K + sq * 4;
    const float* bGm = Wp + (size_t)(col0 + sr) * K + sq * 4;

    float acc[4][8][4];
#pragma unroll
    for (int i = 0; i < 4; i++)
#pragma unroll
        for (int j = 0; j < 8; j++)
#pragma unroll
            for (int q = 0; q < 4; q++) acc[i][j][q] = 0.f;

    const int nst = K / BK;

    // stage layout: A0(16K) A1(16K) B0(32K) B1(32K)
    auto issue = [&](int s) {
        const uint32_t base = sb + (uint32_t)(s & 1) * STG_BYTES;
        const int kOff = s * BK;
#pragma unroll
        for (int blk = 0; blk < 2; blk++) {
#pragma unroll
            for (int i = 0; i < 4; i++)
                cp16(base + blk * A_BLK + stgOff + (uint32_t)(i * 32 * 128),
                     aGm + (size_t)i * 32 * K + kOff + blk * 32);
#pragma unroll
            for (int i = 0; i < 8; i++)
                cp16(base + A_BYTES + blk * B_BLK + stgOff + (uint32_t)(i * 32 * 128),
                     bGm + (size_t)i * 32 * K + kOff + blk * 32);
        }
        cp_commit();
    };

    // fragment ldsm for one kk-slice of the given stage base
    auto load_frags = [&](uint32_t stgA, int kk, uint32_t af[4][4], uint32_t bf[4][4]) {
        const int blk = kk >> 2;
        const int t   = kk & 3;
        const uint32_t sbA = stgA + (uint32_t)(blk * A_BLK) + ktA[t];
        const uint32_t sbB = stgA + A_BYTES + (uint32_t)(blk * B_BLK) + ktB[t];
#pragma unroll
        for (int i = 0; i < 4; ++i)
            ldsm4(af[i][0], af[i][1], af[i][2], af[i][3], sbA + rowA[i]);
#pragma unroll
        for (int j = 0; j < 4; ++j)
            ldsm4(bf[j][0], bf[j][1], bf[j][2], bf[j][3], sbB + rowB[j]);
    };

    issue(0);

    uint32_t afb[2][4][4], bfb[2][4][4];         // double-buffered fragments

    for (int s = 0; s < nst; ++s) {
        cp_wait<0>();
        __syncthreads();                          // buffer s&1 ready, s-1 consumed
        if (s + 1 < nst) issue(s + 1);            // fill the freed buffer

        const uint32_t stgA = sb + (uint32_t)(s & 1) * STG_BYTES;

        load_frags(stgA, 0, afb[0], bfb[0]);      // prime kk=0
#pragma unroll
        for (int kk = 0; kk < 8; ++kk) {
            const int cur = kk & 1;
            if (kk + 1 < 8)                       // prefetch kk+1 during kk MMAs
                load_frags(stgA, kk + 1, afb[cur ^ 1], bfb[cur ^ 1]);
#pragma unroll
            for (int i = 0; i < 4; ++i)
#pragma unroll
                for (int j = 0; j < 4; ++j) {
                    mma_tf32(acc[i][2 * j],     afb[cur][i], bfb[cur][j][0], bfb[cur][j][1]);
                    mma_tf32(acc[i][2 * j + 1], afb[cur][i], bfb[cur][j][2], bfb[cur][j][3]);
                }
        }
    }

    // ---- epilogue: direct float2 stores --------------------------------------
    const int gr  = lane >> 2;
    const int ctg = lane & 3;
#pragma unroll
    for (int j = 0; j < 8; ++j) {
        const int col = col0 + wn * 64 + j * 8 + 2 * ctg;
        float2 bv = *(const float2*)(Bp + col);
#pragma unroll
        for (int i = 0; i < 4; ++i) {
            const int ra = row0 + wm * 64 + i * 16 + gr;
            const int rb = ra + 8;
            float2 o0, o1;
            o0.x = acc[i][j][0] + bv.x;  o0.y = acc[i][j][1] + bv.y;
            o1.x = acc[i][j][2] + bv.x;  o1.y = acc[i][j][3] + bv.y;
            if (RESID) {
                float2 r0 = *(const float2*)(resid + (size_t)ra * OUTD + col);
                float2 r1 = *(const float2*)(resid + (size_t)rb * OUTD + col);
                o0.x += r0.x; o0.y += r0.y;
                o1.x += r1.x; o1.y += r1.y;
            }
            if (GELU) {
                o0.x = gelu_erf(o0.x); o0.y = gelu_erf(o0.y);
                o1.x = gelu_erf(o1.x); o1.y = gelu_erf(o1.y);
            }
            if (ROUND_OUT) {
                o0.x = to_tf32(o0.x); o0.y = to_tf32(o0.y);
                o1.x = to_tf32(o1.x); o1.y = to_tf32(o1.y);
            }
            *(float2*)(C + (size_t)ra * OUTD + col) = o0;
            *(float2*)(C + (size_t)rb * OUTD + col) = o1;
        }
    }
}

// ---------------- launch ------------------------------------------------------
extern "C" void kernel_launch(void* const* d_in, const int* in_sizes, int n_in,
                              void* d_out, int out_size)
{
    const float* x      = (const float*)d_in[0];
    const float* ln_g   = (const float*)d_in[1];
    const float* ln_b   = (const float*)d_in[2];
    const float* attn_w = (const float*)d_in[3];
    const float* attn_b = (const float*)d_in[4];
    /* gate_w d_in[5] unused — gating does not affect the output path */
    const float* fc1_w  = (const float*)d_in[6];
    const float* fc1_b  = (const float*)d_in[7];
    const float* fc2_w  = (const float*)d_in[8];
    const float* fc2_b  = (const float*)d_in[9];
    const float* next_w = (const float*)d_in[10];
    const float* next_b = (const float*)d_in[11];
    float* out = (float*)d_out;

    void *p_norm, *p_xattn, *p_h, *p_y, *p_wr;
    cudaGetSymbolAddress(&p_norm,  g_norm);
    cudaGetSymbolAddress(&p_xattn, g_xattn);
    cudaGetSymbolAddress(&p_h,     g_h);
    cudaGetSymbolAddress(&p_y,     g_y);
    cudaGetSymbolAddress(&p_wr,    g_wr);
    float* norm  = (float*)p_norm;
    float* xattn = (float*)p_xattn;
    float* hbuf  = (float*)p_h;
    float* ybuf  = (float*)p_y;
    float* wr    = (float*)p_wr;

    cudaFuncSetAttribute(tc_gemm<false, true,  true>,
                         cudaFuncAttributeMaxDynamicSharedMemorySize, SMEM_BYTES);
    cudaFuncSetAttribute(tc_gemm<true,  false, true>,
                         cudaFuncAttributeMaxDynamicSharedMemorySize, SMEM_BYTES);
    cudaFuncSetAttribute(tc_gemm<false, false, true>,
                         cudaFuncAttributeMaxDynamicSharedMemorySize, SMEM_BYTES);
    cudaFuncSetAttribute(tc_gemm<true,  false, false>,
                         cudaFuncAttributeMaxDynamicSharedMemorySize, SMEM_BYTES);

    // 0) pre-round all weights to tf32 (single fused launch)
    {
        const size_t total4 = 2 * (size_t)N4_SMALL + 2 * (size_t)N4_BIG;
        round_all<<<(unsigned)((total4 + 255) / 256), 256>>>(
            (const float4*)attn_w, (const float4*)next_w,
            (const float4*)fc1_w,  (const float4*)fc2_w, (float4*)wr);
    }

    // 1) LayerNorm (tf32-rounded output)
    ln_kernel<<<NTOK / 8, 256>>>(x, ln_g, ln_b, norm);

    // 2) attn linear + residual (output rounded: feeds fc1)
    tc_gemm<false, true, true><<<dim3(DMODEL / BN, NTOK / BM), THREADS, SMEM_BYTES>>>(
        norm, wr + WR_ATTN, attn_b, x, xattn, DMODEL, DMODEL, 0, 0);

    // 3) fc1 + gelu (per-expert; output rounded: feeds fc2)
    tc_gemm<true, false, true><<<dim3(HID / BN, NTOK / BM), THREADS, SMEM_BYTES>>>(
        xattn, wr + WR_FC1, fc1_b, nullptr, hbuf, DMODEL, HID,
        (size_t)HID * DMODEL, HID);

    // 4) fc2 (per-expert; output rounded: feeds next)
    tc_gemm<false, false, true><<<dim3(DMODEL / BN, NTOK / BM), THREADS, SMEM_BYTES>>>(
        hbuf, wr + WR_FC2, fc2_b, nullptr, ybuf, HID, DMODEL,
        (size_t)DMODEL * HID, DMODEL);

    // 5) next linear + gelu (final output, no rounding)
    tc_gemm<true, false, false><<<dim3(DMODEL / BN, NTOK / BM), THREADS, SMEM_BYTES>>>(
        ybuf, wr + WR_NEXT, next_b, nullptr, out, DMODEL, DMODEL, 0, 0);
}